// round 17
// baseline (speedup 1.0000x reference)
#include <cuda_runtime.h>
#include <cuda_fp16.h>
#include <math.h>

#define BB 8
#define TT 512
#define DD 768
#define HH 12
#define DHH 64
#define FF 3072
#define LL 12
#define BT (BB*TT)      // 4096
#define ZZ (BB*HH)      // 96

// ---------------- scratch (device globals; no allocation) ----------------
__device__ float g_hbase[BT*DD];
__device__ float g_p[BT*2];
__device__ float g_s[BT];
__device__ float g_h[BT*DD];
__device__ float g_attnout[BT*DD];
__device__ float g_hmid[BT*DD];
__device__ float g_ffn2[BT*DD];
// fp16 buffers
__device__ __half g_h16[BT*DD];
__device__ __half g_q16[BT*DD];
__device__ __half g_k16[BT*DD];
__device__ __half g_v16[BT*DD];
__device__ __half g_ctx16[BT*DD];
__device__ __half g_hmid16[BT*DD];
__device__ __half g_ffn116[(size_t)BT*FF];
__device__ __half g_wq16[(size_t)LL*DD*DD];
__device__ __half g_wk16[(size_t)LL*DD*DD];
__device__ __half g_wv16[(size_t)LL*DD*DD];
__device__ __half g_wo16[(size_t)LL*DD*DD];
__device__ __half g_w116[(size_t)LL*FF*DD];
__device__ __half g_w216[(size_t)LL*FF*DD];

__device__ __forceinline__ __half2 f2h2v(float x, float y) {
    return __halves2half2(__float2half_rn(x), __float2half_rn(y));
}

__device__ __forceinline__ unsigned su32(const void* p) {
    unsigned a;
    asm("{ .reg .u64 t; cvta.to.shared.u64 t, %1; cvt.u32.u64 %0, t; }"
        : "=r"(a) : "l"(p));
    return a;
}

__device__ __forceinline__ void mma16h(float* c, unsigned a0, unsigned a1,
                                       unsigned a2, unsigned a3,
                                       unsigned b0, unsigned b1) {
    asm volatile(
        "mma.sync.aligned.m16n8k16.row.col.f32.f16.f16.f32 "
        "{%0,%1,%2,%3},{%4,%5,%6,%7},{%8,%9},{%0,%1,%2,%3};"
        : "+f"(c[0]), "+f"(c[1]), "+f"(c[2]), "+f"(c[3])
        : "r"(a0), "r"(a1), "r"(a2), "r"(a3), "r"(b0), "r"(b1));
}

#define LDM_X4(r0, r1, r2, r3, addr) \
    asm volatile("ldmatrix.sync.aligned.m8n8.x4.shared.b16 {%0,%1,%2,%3}, [%4];" \
        : "=r"(r0), "=r"(r1), "=r"(r2), "=r"(r3) : "r"(addr))

#define LDM_X4_T(r0, r1, r2, r3, addr) \
    asm volatile("ldmatrix.sync.aligned.m8n8.x4.trans.shared.b16 {%0,%1,%2,%3}, [%4];" \
        : "=r"(r0), "=r"(r1), "=r"(r2), "=r"(r3) : "r"(addr))

// ---------------- f32 -> f16 conversion (weights, once per launch) ----------------
__global__ void cvt16_kernel(const float* __restrict__ s, __half* __restrict__ d, int n) {
    int i = (blockIdx.x * 256 + threadIdx.x) * 4;
    if (i >= n) return;
    float4 v = *(const float4*)(s + i);
    *(__half2*)&d[i]     = f2h2v(v.x, v.y);
    *(__half2*)&d[i + 2] = f2h2v(v.z, v.w);
}

// =============== fp16 tensor-core NT GEMM (BK=32, ldmatrix, dynamic smem) ===============
// C[M,N] = A[M,K] @ B[N,K]^T. CTA 128x128, warp 64x64 (2x2 warps, 128 thr), BK=32.
// Rows of 72 halves (36 words ≡ 4 mod 32): ldmatrix rows on distinct banks.
#define KR 72
#define HG_SMEM (4*128*KR*2)   // 2 bufs x (A+B) x 128 rows x 72 halves x 2B = 73728
template<bool FUSE3>
__global__ void __launch_bounds__(128) hgemm_nt(
    const __half* __restrict__ Ag, const __half* __restrict__ Bg,
    const __half* __restrict__ B1g, const __half* __restrict__ B2g,
    const float* __restrict__ bias, float* __restrict__ Cf,
    __half* __restrict__ C16, __half* __restrict__ C116, __half* __restrict__ C216,
    int K, int lda, int ldb, int ldc, int act)
{
    constexpr int BM = 128, BN = 128, BK = 32;
    constexpr int MI = 4, NI = 8;

    extern __shared__ __align__(16) __half dynsm[];
    __half* As = dynsm;                  // [2][BM][KR]
    __half* Bs = dynsm + 2*BM*KR;        // [2][BN][KR]

    const int z = blockIdx.z;
    const __half* B; __half* Ch;
    if constexpr (FUSE3) {
        B  = (z == 0) ? Bg  : (z == 1) ? B1g  : B2g;
        Ch = (z == 0) ? C16 : (z == 1) ? C116 : C216;
    } else { B = Bg; Ch = C16; }

    const int m0 = blockIdx.y * BM;
    const int n0 = blockIdx.x * BN;
    const int tid = threadIdx.x;
    const int warp = tid >> 5, lane = tid & 31;
    const int wm = warp & 1, wn = warp >> 1;
    const int g = lane >> 2, tig = lane & 3;

    const int grp = lane >> 3, within = lane & 7;
    const int aoff = (within + (grp & 1)*8)*KR + (grp >> 1)*8;
    const int boff = (within + (grp >> 1)*8)*KR + (grp & 1)*8;
    const unsigned sbA = su32(As);
    const unsigned sbB = su32(Bs);

    // staging: 2 threads/row x 16 halves (2x uint4), 64 rows/pass, 2 passes
    const int ar = tid >> 1;
    const int ak = (tid & 1) * 16;
    uint4 pa[2][2], pb[2][2];

    auto fetchA = [&](int k0) {
#pragma unroll
        for (int i = 0; i < 2; i++) {
            const __half* s = Ag + (size_t)(m0 + ar + i*64)*lda + k0 + ak;
            pa[i][0] = *(const uint4*)s;
            pa[i][1] = *(const uint4*)(s + 8);
        }
    };
    auto fetchB = [&](int k0) {
#pragma unroll
        for (int i = 0; i < 2; i++) {
            const __half* s = B + (size_t)(n0 + ar + i*64)*ldb + k0 + ak;
            pb[i][0] = *(const uint4*)s;
            pb[i][1] = *(const uint4*)(s + 8);
        }
    };
    auto stage = [&](int buf) {
#pragma unroll
        for (int i = 0; i < 2; i++) {
            __half* d = &As[(size_t)buf*BM*KR + (ar + i*64)*KR + ak];
            *(uint4*)d = pa[i][0]; *(uint4*)(d + 8) = pa[i][1];
            __half* e = &Bs[(size_t)buf*BN*KR + (ar + i*64)*KR + ak];
            *(uint4*)e = pb[i][0]; *(uint4*)(e + 8) = pb[i][1];
        }
    };

    float acc[MI][NI][4];
#pragma unroll
    for (int mi = 0; mi < MI; mi++)
#pragma unroll
        for (int ni = 0; ni < NI; ni++)
#pragma unroll
            for (int r = 0; r < 4; r++) acc[mi][ni][r] = 0.f;

    auto compute = [&](int buf) {
#pragma unroll
        for (int kbk = 0; kbk < 2; kbk++) {
            unsigned af[MI][4];
#pragma unroll
            for (int mi = 0; mi < MI; mi++) {
                unsigned addr = sbA + (unsigned)(buf*BM*KR + (wm*64 + mi*16)*KR + kbk*16 + aoff)*2u;
                LDM_X4(af[mi][0], af[mi][1], af[mi][2], af[mi][3], addr);
            }
            unsigned bf[NI][2];
#pragma unroll
            for (int ni = 0; ni < NI; ni += 2) {
                unsigned addr = sbB + (unsigned)(buf*BN*KR + (wn*64 + ni*8)*KR + kbk*16 + boff)*2u;
                LDM_X4(bf[ni][0], bf[ni][1], bf[ni+1][0], bf[ni+1][1], addr);
            }
#pragma unroll
            for (int mi = 0; mi < MI; mi++)
#pragma unroll
                for (int ni = 0; ni < NI; ni++)
                    mma16h(acc[mi][ni], af[mi][0], af[mi][1], af[mi][2], af[mi][3],
                           bf[ni][0], bf[ni][1]);
        }
    };

    fetchA(0); fetchB(0);
    stage(0);
    __syncthreads();
    int buf = 0;
    const int nk = K / BK;
    for (int it = 1; it < nk; it++) {
        fetchA(it*BK); fetchB(it*BK);
        compute(buf);
        stage(buf ^ 1);
        __syncthreads();
        buf ^= 1;
    }
    compute(buf);

#pragma unroll
    for (int mi = 0; mi < MI; mi++) {
        int row0 = m0 + wm*64 + mi*16 + g;
#pragma unroll
        for (int ni = 0; ni < NI; ni++) {
            int col = n0 + wn*64 + ni*8 + tig*2;
            float c0 = acc[mi][ni][0], c1 = acc[mi][ni][1];
            float c2 = acc[mi][ni][2], c3 = acc[mi][ni][3];
            if (bias) {
                float b0 = bias[col], b1 = bias[col+1];
                c0 += b0; c1 += b1; c2 += b0; c3 += b1;
            }
            if (act) {
                c0 = 0.5f*c0*(1.f + erff(c0*0.70710678118654752f));
                c1 = 0.5f*c1*(1.f + erff(c1*0.70710678118654752f));
                c2 = 0.5f*c2*(1.f + erff(c2*0.70710678118654752f));
                c3 = 0.5f*c3*(1.f + erff(c3*0.70710678118654752f));
            }
            if (Cf) {
                *(float2*)&Cf[(size_t)row0*ldc + col]      = make_float2(c0, c1);
                *(float2*)&Cf[(size_t)(row0+8)*ldc + col]  = make_float2(c2, c3);
            }
            if (Ch) {
                *(__half2*)&Ch[(size_t)row0*ldc + col]      = f2h2v(c0, c1);
                *(__half2*)&Ch[(size_t)(row0+8)*ldc + col]  = f2h2v(c2, c3);
            }
        }
    }
}

// =============== fused flash attention (fp16 tensor cores; round-16) ===============
#define VROW 72
__global__ void __launch_bounds__(128) flash_attn_kernel(
        const float* __restrict__ compat_l, const float* __restrict__ gamma_l,
        const int* __restrict__ mask)
{
    __shared__ __align__(16) __half Qs[64*VROW];
    __shared__ __align__(16) __half Ks[64*VROW];
    __shared__ __align__(16) __half Vs[64*VROW];
    __shared__ __align__(16) __half Ps[4][16*VROW];
    __shared__ float pj0[64], pj1[64], cj[64];

    const int z = blockIdx.y, b = z / HH, hh = z % HH;
    const int i0 = blockIdx.x * 64;
    const int tid = threadIdx.x, w = tid >> 5, lane = tid & 31;
    const int g = lane >> 2, tig = lane & 3;
    const int grp = lane >> 3, within = lane & 7;
    const int moff = (within + (grp & 1)*8)*VROW + (grp >> 1)*8;
    const int boff = (within + (grp >> 1)*8)*VROW + (grp & 1)*8;

    const unsigned sbQ = su32(Qs), sbK = su32(Ks), sbV = su32(Vs);
    const unsigned sbP = su32(&Ps[w][0]);

    const __half* qb = g_q16 + (size_t)(b*TT)*DD + hh*DHH;
    const __half* kb = g_k16 + (size_t)(b*TT)*DD + hh*DHH;
    const __half* vb = g_v16 + (size_t)(b*TT)*DD + hh*DHH;

    const int lr = tid >> 3, lc = (tid & 7)*8;
#pragma unroll
    for (int p = 0; p < 4; p++) {
        int row = p*16 + lr;
        *(uint4*)&Qs[row*VROW + lc] = *(const uint4*)(qb + (size_t)(i0+row)*DD + lc);
    }
    __syncthreads();

    unsigned aq[4][4];
#pragma unroll
    for (int kbk = 0; kbk < 4; kbk++) {
        unsigned addr = sbQ + (unsigned)((w*16)*VROW + kbk*16 + moff)*2u;
        LDM_X4(aq[kbk][0], aq[kbk][1], aq[kbk][2], aq[kbk][3], addr);
    }

    const int gi0 = b*TT + i0 + w*16 + g;
    const float pi00 = g_p[gi0*2],       pi01 = g_p[gi0*2+1];
    const float pi10 = g_p[(gi0+8)*2],   pi11 = g_p[(gi0+8)*2+1];
    const float C00 = compat_l[hh*4+0], C01 = compat_l[hh*4+1];
    const float C10 = compat_l[hh*4+2], C11 = compat_l[hh*4+3];
    const float cp0_0 = pi00*C00 + pi01*C10, cp1_0 = pi00*C01 + pi01*C11;
    const float cp0_1 = pi10*C00 + pi11*C10, cp1_1 = pi10*C01 + pi11*C11;
    const float gm = gamma_l[0];

    float m0 = -1e30f, m1 = -1e30f, l0 = 0.f, l1 = 0.f;
    float oacc[8][4];
#pragma unroll
    for (int ni = 0; ni < 8; ni++)
#pragma unroll
        for (int r = 0; r < 4; r++) oacc[ni][r] = 0.f;

    __half* Pw = &Ps[w][0];

    for (int jt = 0; jt < 8; jt++) {
        __syncthreads();
        const int j0 = jt * 64;
#pragma unroll
        for (int p = 0; p < 4; p++) {
            int row = p*16 + lr;
            *(uint4*)&Ks[row*VROW + lc] = *(const uint4*)(kb + (size_t)(j0+row)*DD + lc);
            *(uint4*)&Vs[row*VROW + lc] = *(const uint4*)(vb + (size_t)(j0+row)*DD + lc);
        }
        if (tid < 64) {
            int jg = b*TT + j0 + tid;
            pj0[tid] = g_p[jg*2];
            pj1[tid] = g_p[jg*2+1];
            cj[tid]  = gm*g_s[jg] + (1.f - (float)mask[jg]) * -10000.f;
        }
        __syncthreads();

        float sacc[8][4];
#pragma unroll
        for (int ni = 0; ni < 8; ni++)
#pragma unroll
            for (int r = 0; r < 4; r++) sacc[ni][r] = 0.f;
#pragma unroll
        for (int kbk = 0; kbk < 4; kbk++) {
            unsigned bf[8][2];
#pragma unroll
            for (int ni = 0; ni < 8; ni += 2) {
                unsigned addr = sbK + (unsigned)((ni*8)*VROW + kbk*16 + boff)*2u;
                LDM_X4(bf[ni][0], bf[ni][1], bf[ni+1][0], bf[ni+1][1], addr);
            }
#pragma unroll
            for (int ni = 0; ni < 8; ni++)
                mma16h(sacc[ni], aq[kbk][0], aq[kbk][1], aq[kbk][2], aq[kbk][3],
                       bf[ni][0], bf[ni][1]);
        }

        float rm0 = -1e30f, rm1 = -1e30f;
#pragma unroll
        for (int ni = 0; ni < 8; ni++) {
#pragma unroll
            for (int c = 0; c < 2; c++) {
                int jj = ni*8 + 2*tig + c;
                float bj0 = pj0[jj], bj1 = pj1[jj], bc = cj[jj];
                sacc[ni][c]   = sacc[ni][c]  *0.125f + cp0_0*bj0 + cp1_0*bj1 + bc;
                sacc[ni][2+c] = sacc[ni][2+c]*0.125f + cp0_1*bj0 + cp1_1*bj1 + bc;
                rm0 = fmaxf(rm0, sacc[ni][c]);
                rm1 = fmaxf(rm1, sacc[ni][2+c]);
            }
        }
        rm0 = fmaxf(rm0, __shfl_xor_sync(0xffffffffu, rm0, 1));
        rm0 = fmaxf(rm0, __shfl_xor_sync(0xffffffffu, rm0, 2));
        rm1 = fmaxf(rm1, __shfl_xor_sync(0xffffffffu, rm1, 1));
        rm1 = fmaxf(rm1, __shfl_xor_sync(0xffffffffu, rm1, 2));

        float mn0 = fmaxf(m0, rm0), mn1 = fmaxf(m1, rm1);
        float sc0 = expf(m0 - mn0), sc1 = expf(m1 - mn1);
        float rs0 = 0.f, rs1 = 0.f;
#pragma unroll
        for (int ni = 0; ni < 8; ni++) {
            int jj = ni*8 + 2*tig;
            float p00 = expf(sacc[ni][0] - mn0);
            float p01 = expf(sacc[ni][1] - mn0);
            float p10 = expf(sacc[ni][2] - mn1);
            float p11 = expf(sacc[ni][3] - mn1);
            rs0 += p00 + p01; rs1 += p10 + p11;
            *(__half2*)&Pw[ g     *VROW + jj] = f2h2v(p00, p01);
            *(__half2*)&Pw[(g + 8)*VROW + jj] = f2h2v(p10, p11);
        }
        rs0 += __shfl_xor_sync(0xffffffffu, rs0, 1);
        rs0 += __shfl_xor_sync(0xffffffffu, rs0, 2);
        rs1 += __shfl_xor_sync(0xffffffffu, rs1, 1);
        rs1 += __shfl_xor_sync(0xffffffffu, rs1, 2);
        l0 = l0*sc0 + rs0; l1 = l1*sc1 + rs1;
        m0 = mn0; m1 = mn1;
#pragma unroll
        for (int ni = 0; ni < 8; ni++) {
            oacc[ni][0] *= sc0; oacc[ni][1] *= sc0;
            oacc[ni][2] *= sc1; oacc[ni][3] *= sc1;
        }
        __syncwarp();

#pragma unroll
        for (int kbk = 0; kbk < 4; kbk++) {
            unsigned ap[4];
            LDM_X4(ap[0], ap[1], ap[2], ap[3],
                   sbP + (unsigned)(kbk*16 + moff)*2u);
            unsigned bv[8][2];
#pragma unroll
            for (int ni = 0; ni < 8; ni += 2) {
                unsigned addr = sbV + (unsigned)((kbk*16)*VROW + ni*8 + moff)*2u;
                LDM_X4_T(bv[ni][0], bv[ni][1], bv[ni+1][0], bv[ni+1][1], addr);
            }
#pragma unroll
            for (int ni = 0; ni < 8; ni++)
                mma16h(oacc[ni], ap[0], ap[1], ap[2], ap[3], bv[ni][0], bv[ni][1]);
        }
        __syncwarp();
    }

    float inv0 = 1.f / l0, inv1 = 1.f / l1;
    const size_t r0 = (size_t)(b*TT + i0 + w*16 + g) * DD + hh*DHH;
#pragma unroll
    for (int ni = 0; ni < 8; ni++) {
        int col = ni*8 + 2*tig;
        *(__half2*)&g_ctx16[r0 + col]        = f2h2v(oacc[ni][0]*inv0, oacc[ni][1]*inv0);
        *(__half2*)&g_ctx16[r0 + 8*DD + col] = f2h2v(oacc[ni][2]*inv1, oacc[ni][3]*inv1);
    }
}

// ---------------- stage 1 kernels ----------------
__global__ void embed_base_kernel(const int* __restrict__ ids,
                                  const float* __restrict__ tok,
                                  const float* __restrict__ pos,
                                  const float* __restrict__ proto,
                                  const float* __restrict__ log_tau) {
    int row = blockIdx.x;
    int t = row % TT;
    int id = ids[row];
    const float* trow = tok + (size_t)id * DD;
    const float* prow = pos + (size_t)t * DD;
    float a0 = 0.f, a1 = 0.f;
    __shared__ float r0[256], r1[256];
    for (int d = threadIdx.x; d < DD; d += 256) {
        float v = trow[d] + prow[d];
        g_hbase[(size_t)row*DD + d] = v;
        a0 += v * proto[d];
        a1 += v * proto[DD + d];
    }
    r0[threadIdx.x] = a0; r1[threadIdx.x] = a1;
    __syncthreads();
    for (int s = 128; s > 0; s >>= 1) {
        if (threadIdx.x < s) {
            r0[threadIdx.x] += r0[threadIdx.x + s];
            r1[threadIdx.x] += r1[threadIdx.x + s];
        }
        __syncthreads();
    }
    if (threadIdx.x == 0) {
        float tau = fmaxf(expf(log_tau[0]), 0.25f);
        float l0 = r0[0] / tau, l1 = r1[0] / tau;
        float m = fmaxf(l0, l1);
        float e0 = expf(l0 - m), e1 = expf(l1 - m);
        float inv = 1.f / (e0 + e1);
        g_p[row*2 + 0] = e0 * inv;
        g_p[row*2 + 1] = e1 * inv;
    }
}

__global__ void switch_kernel() {
    int i = blockIdx.x * blockDim.x + threadIdx.x;
    if (i >= BT) return;
    int t = i % TT;
    float sv = 0.f;
    if (t > 0)
        sv = 1.f - (g_p[i*2]*g_p[(i-1)*2] + g_p[i*2+1]*g_p[(i-1)*2+1]);
    g_s[i] = sv;
}

__global__ void embed_ln_kernel(const float* __restrict__ lang,
                                const float* __restrict__ sw,
                                const float* __restrict__ w,
                                const float* __restrict__ b) {
    int row = blockIdx.x;
    __shared__ float rs[256], rq[256];
    float p0 = g_p[row*2], p1 = g_p[row*2+1], sv = g_s[row];
    float4 xv = make_float4(0.f, 0.f, 0.f, 0.f);
    float sum = 0.f, sq = 0.f;
    int d = threadIdx.x * 4;
    if (threadIdx.x < 192) {
        float4 hb = *(const float4*)(g_hbase + (size_t)row*DD + d);
        float4 lg0 = *(const float4*)(lang + d);
        float4 lg1 = *(const float4*)(lang + DD + d);
        float4 sw4 = *(const float4*)(sw + d);
        xv.x = hb.x + p0*lg0.x + p1*lg1.x + sv*sw4.x;
        xv.y = hb.y + p0*lg0.y + p1*lg1.y + sv*sw4.y;
        xv.z = hb.z + p0*lg0.z + p1*lg1.z + sv*sw4.z;
        xv.w = hb.w + p0*lg0.w + p1*lg1.w + sv*sw4.w;
        sum = xv.x + xv.y + xv.z + xv.w;
        sq  = xv.x*xv.x + xv.y*xv.y + xv.z*xv.z + xv.w*xv.w;
    }
    rs[threadIdx.x] = sum; rq[threadIdx.x] = sq;
    __syncthreads();
    for (int s = 128; s > 0; s >>= 1) {
        if (threadIdx.x < s) { rs[threadIdx.x]+=rs[threadIdx.x+s]; rq[threadIdx.x]+=rq[threadIdx.x+s]; }
        __syncthreads();
    }
    float mu = rs[0] * (1.f/DD);
    float var = rq[0] * (1.f/DD) - mu*mu;
    float rstd = rsqrtf(var + 1e-12f);
    if (threadIdx.x < 192) {
        float4 w4 = *(const float4*)(w + d);
        float4 b4 = *(const float4*)(b + d);
        float v0 = (xv.x-mu)*rstd*w4.x + b4.x;
        float v1 = (xv.y-mu)*rstd*w4.y + b4.y;
        float v2 = (xv.z-mu)*rstd*w4.z + b4.z;
        float v3 = (xv.w-mu)*rstd*w4.w + b4.w;
        *(float4*)(g_h + (size_t)row*DD + d) = make_float4(v0, v1, v2, v3);
        *(__half2*)(g_h16 + (size_t)row*DD + d)     = f2h2v(v0, v1);
        *(__half2*)(g_h16 + (size_t)row*DD + d + 2) = f2h2v(v2, v3);
    }
}

__global__ void ln_residual_kernel(const float* __restrict__ a,
                                   const float* __restrict__ bres,
                                   const float* __restrict__ w,
                                   const float* __restrict__ bias,
                                   float* __restrict__ out,
                                   __half* __restrict__ out16) {
    int row = blockIdx.x;
    __shared__ float rs[256], rq[256];
    float4 xv = make_float4(0.f, 0.f, 0.f, 0.f);
    float sum = 0.f, sq = 0.f;
    int d = threadIdx.x * 4;
    if (threadIdx.x < 192) {
        float4 av = *(const float4*)(a + (size_t)row*DD + d);
        float4 bv = *(const float4*)(bres + (size_t)row*DD + d);
        xv = make_float4(av.x+bv.x, av.y+bv.y, av.z+bv.z, av.w+bv.w);
        sum = xv.x + xv.y + xv.z + xv.w;
        sq  = xv.x*xv.x + xv.y*xv.y + xv.z*xv.z + xv.w*xv.w;
    }
    rs[threadIdx.x] = sum; rq[threadIdx.x] = sq;
    __syncthreads();
    for (int s = 128; s > 0; s >>= 1) {
        if (threadIdx.x < s) { rs[threadIdx.x]+=rs[threadIdx.x+s]; rq[threadIdx.x]+=rq[threadIdx.x+s]; }
        __syncthreads();
    }
    float mu = rs[0] * (1.f/DD);
    float var = rq[0] * (1.f/DD) - mu*mu;
    float rstd = rsqrtf(var + 1e-12f);
    if (threadIdx.x < 192) {
        float4 w4 = *(const float4*)(w + d);
        float4 b4 = *(const float4*)(bias + d);
        float v0 = (xv.x-mu)*rstd*w4.x + b4.x;
        float v1 = (xv.y-mu)*rstd*w4.y + b4.y;
        float v2 = (xv.z-mu)*rstd*w4.z + b4.z;
        float v3 = (xv.w-mu)*rstd*w4.w + b4.w;
        *(float4*)(out + (size_t)row*DD + d) = make_float4(v0, v1, v2, v3);
        if (out16) {
            *(__half2*)(out16 + (size_t)row*DD + d)     = f2h2v(v0, v1);
            *(__half2*)(out16 + (size_t)row*DD + d + 2) = f2h2v(v2, v3);
        }
    }
}

// ---------------- host launch ----------------
extern "C" void kernel_launch(void* const* d_in, const int* in_sizes, int n_in,
                              void* d_out, int out_size) {
    const int*   ids      = (const int*)  d_in[0];
    const int*   mask     = (const int*)  d_in[1];
    const float* tok      = (const float*)d_in[2];
    const float* pos      = (const float*)d_in[3];
    const float* lang     = (const float*)d_in[4];
    const float* sw       = (const float*)d_in[5];
    const float* proto    = (const float*)d_in[6];
    const float* log_tau  = (const float*)d_in[7];
    const float* eln_w    = (const float*)d_in[8];
    const float* eln_b    = (const float*)d_in[9];
    const float* Wq       = (const float*)d_in[10];
    const float* Wk       = (const float*)d_in[11];
    const float* Wv       = (const float*)d_in[12];
    const float* Wo       = (const float*)d_in[13];
    const float* Wob      = (const float*)d_in[14];
    const float* compat   = (const float*)d_in[15];
    const float* gamma    = (const float*)d_in[16];
    const float* W1       = (const float*)d_in[17];
    const float* b1       = (const float*)d_in[18];
    const float* W2       = (const float*)d_in[19];
    const float* b2       = (const float*)d_in[20];
    const float* ln1w     = (const float*)d_in[21];
    const float* ln1b     = (const float*)d_in[22];
    const float* ln2w     = (const float*)d_in[23];
    const float* ln2b     = (const float*)d_in[24];
    float* out = (float*)d_out;

    float *h, *attnout, *hmid, *ffn2;
    __half *h16, *q16, *k16, *v16, *ctx16, *hmid16, *ffn116;
    __half *wq16, *wk16, *wv16, *wo16, *w116, *w216;
    cudaGetSymbolAddress((void**)&h,       g_h);
    cudaGetSymbolAddress((void**)&attnout, g_attnout);
    cudaGetSymbolAddress((void**)&hmid,    g_hmid);
    cudaGetSymbolAddress((void**)&ffn2,    g_ffn2);
    cudaGetSymbolAddress((void**)&h16,     g_h16);
    cudaGetSymbolAddress((void**)&q16,     g_q16);
    cudaGetSymbolAddress((void**)&k16,     g_k16);
    cudaGetSymbolAddress((void**)&v16,     g_v16);
    cudaGetSymbolAddress((void**)&ctx16,   g_ctx16);
    cudaGetSymbolAddress((void**)&hmid16,  g_hmid16);
    cudaGetSymbolAddress((void**)&ffn116,  g_ffn116);
    cudaGetSymbolAddress((void**)&wq16,    g_wq16);
    cudaGetSymbolAddress((void**)&wk16,    g_wk16);
    cudaGetSymbolAddress((void**)&wv16,    g_wv16);
    cudaGetSymbolAddress((void**)&wo16,    g_wo16);
    cudaGetSymbolAddress((void**)&w116,    g_w116);
    cudaGetSymbolAddress((void**)&w216,    g_w216);

    cudaFuncSetAttribute(hgemm_nt<true>,
                         cudaFuncAttributeMaxDynamicSharedMemorySize, HG_SMEM);
    cudaFuncSetAttribute(hgemm_nt<false>,
                         cudaFuncAttributeMaxDynamicSharedMemorySize, HG_SMEM);

    // weight conversion (once per launch)
    const int nDD = LL*DD*DD, nFD = LL*FF*DD;
    cvt16_kernel<<<nDD/1024, 256>>>(Wq, wq16, nDD);
    cvt16_kernel<<<nDD/1024, 256>>>(Wk, wk16, nDD);
    cvt16_kernel<<<nDD/1024, 256>>>(Wv, wv16, nDD);
    cvt16_kernel<<<nDD/1024, 256>>>(Wo, wo16, nDD);
    cvt16_kernel<<<nFD/1024, 256>>>(W1, w116, nFD);
    cvt16_kernel<<<nFD/1024, 256>>>(W2, w216, nFD);

    embed_base_kernel<<<BT, 256>>>(ids, tok, pos, proto, log_tau);
    switch_kernel<<<(BT + 255)/256, 256>>>();
    embed_ln_kernel<<<BT, 256>>>(lang, sw, eln_w, eln_b);

    const dim3 gQKV(DD/128, BT/128, 3);         // 576
    const dim3 gDense(DD/128, BT/128, 1);       // 192
    const dim3 gFfn1(FF/128, BT/128, 1);        // 768
    const dim3 gFlash(TT/64, ZZ);               // 8 x 96

    for (int l = 0; l < LL; l++) {
        const size_t wdd = (size_t)l * DD * DD;
        const size_t wfd = (size_t)l * FF * DD;
        // fused QKV -> fp16 q/k/v
        hgemm_nt<true><<<gQKV, 128, HG_SMEM>>>(h16, wq16 + wdd, wk16 + wdd, wv16 + wdd,
            nullptr, nullptr, q16, k16, v16, DD, DD, DD, DD, 0);

        // fused attention (fp16 tensor cores) -> ctx16
        flash_attn_kernel<<<gFlash, 128>>>(
            compat + (size_t)l*HH*4, gamma + l, mask);

        // Wo -> f32 attnout
        hgemm_nt<false><<<gDense, 128, HG_SMEM>>>(ctx16, wo16 + wdd, nullptr, nullptr,
            Wob + (size_t)l*DD, attnout, nullptr, nullptr, nullptr, DD, DD, DD, DD, 0);
        ln_residual_kernel<<<BT, 256>>>(h, attnout, ln1w + (size_t)l*DD, ln1b + (size_t)l*DD,
                                        hmid, hmid16);

        // FFN1 (gelu) -> fp16 only
        hgemm_nt<false><<<gFfn1, 128, HG_SMEM>>>(hmid16, w116 + wfd, nullptr, nullptr,
            b1 + (size_t)l*FF, nullptr, ffn116, nullptr, nullptr, DD, DD, DD, FF, 1);
        // FFN2 -> f32
        hgemm_nt<false><<<gDense, 128, HG_SMEM>>>(ffn116, w216 + wfd, nullptr, nullptr,
            b2 + (size_t)l*DD, ffn2, nullptr, nullptr, nullptr, FF, FF, FF, DD, 0);

        float* hout = (l == LL-1) ? out : h;
        ln_residual_kernel<<<BT, 256>>>(hmid, ffn2, ln2w + (size_t)l*DD, ln2b + (size_t)l*DD,
                                        hout, h16);
    }
}